// round 17
// baseline (speedup 1.0000x reference)
#include <cuda_runtime.h>
#include <cuda_fp16.h>
#include <math.h>
#include <stdint.h>

#define NN 50000
#define EE 800000
#define HIDC 128
#define FFC 256
#define NLAYERS 6
#define EPSLN 1e-5f

// ---------------- scratch (device globals; no allocation allowed) ----------------
__device__ float g_z[NN * HIDC];
__device__ float g_q[NN * HIDC];
__device__ float g_k[NN * HIDC];
__device__ float g_v[NN * HIDC];
__device__ float g_sk[NN * HIDC];
__device__ float g_h[NN * HIDC];
__device__ float g_u[NN * HIDC];
__device__ int g_src[EE];
__device__ int g_dst[EE];
__device__ int g_deg[NN];
__device__ int g_rowptr[NN + 1];
__device__ int g_cur[NN];
__device__ int g_csrc[EE];
__device__ int g_csums[128];
__device__ float g_betas[NLAYERS + 2];
__device__ int g_flag[1];

// fp16-preconverted weights, FRAGMENT-MAJOR (m16n8k16) layout; element offsets
#define OFF_WQ  16384
#define OFF_WK  (OFF_WQ + NLAYERS * HIDC * HIDC)
#define OFF_WV  (OFF_WK + NLAYERS * HIDC * HIDC)
#define OFF_WSK (OFF_WV + NLAYERS * HIDC * HIDC)
#define OFF_W1  (OFF_WSK + NLAYERS * HIDC * HIDC)
#define OFF_W2  (OFF_W1 + NLAYERS * HIDC * FFC)
#define TOTW    (OFF_W2 + NLAYERS * FFC * HIDC)
__device__ __half g_wt[TOTW];

#define CHUNK 512
#define NCHK ((NN + CHUNK - 1) / CHUNK)   // 98

// ---------------- helpers ----------------
__device__ __forceinline__ void mma_f16(float* d, const uint32_t* a, const uint32_t* b) {
    asm volatile(
        "mma.sync.aligned.m16n8k16.row.col.f32.f16.f16.f32 "
        "{%0,%1,%2,%3}, {%4,%5,%6,%7}, {%8,%9}, {%0,%1,%2,%3};"
        : "+f"(d[0]), "+f"(d[1]), "+f"(d[2]), "+f"(d[3])
        : "r"(a[0]), "r"(a[1]), "r"(a[2]), "r"(a[3]), "r"(b[0]), "r"(b[1]));
}

__device__ __forceinline__ void cp16(uint32_t saddr, const void* g) {
    asm volatile("cp.async.ca.shared.global [%0], [%1], 16;" ::"r"(saddr), "l"(g));
}
__device__ __forceinline__ void cp_commit() { asm volatile("cp.async.commit_group;"); }
__device__ __forceinline__ void cp_wait0() { asm volatile("cp.async.wait_group 0;"); }

// ---------------- edge index dtype sniff + convert ----------------
__global__ void sniff_kernel(const unsigned* __restrict__ w) {
    if (threadIdx.x == 0 && blockIdx.x == 0) {
        int is64 = 1;
        for (int i = 1; i < 64; i += 2)
            if (w[i] != 0u) { is64 = 0; break; }
        g_flag[0] = is64;
    }
}

__global__ __launch_bounds__(256) void convert_edges(const void* __restrict__ ei) {
    int e = blockIdx.x * blockDim.x + threadIdx.x;
    if (e >= EE) return;
    if (g_flag[0]) {
        const long long* p = (const long long*)ei;
        g_src[e] = (int)p[e];
        g_dst[e] = (int)p[EE + e];
    } else {
        const int* p = (const int*)ei;
        g_src[e] = p[e];
        g_dst[e] = p[EE + e];
    }
}

__global__ void beta_softmax(const float* __restrict__ beta) {
    if (threadIdx.x == 0 && blockIdx.x == 0) {
        float m = -1e30f;
        for (int i = 0; i < NLAYERS + 1; i++) m = fmaxf(m, beta[i]);
        float s = 0.f;
        for (int i = 0; i < NLAYERS + 1; i++) {
            float e = expf(beta[i] - m);
            g_betas[i] = e;
            s += e;
        }
        for (int i = 0; i < NLAYERS + 1; i++) g_betas[i] /= s;
    }
}

// ---------------- weight fp16 convert + m16n8k16 fragment-major permute -------
__device__ __forceinline__ int permW16(int k, int n, int N) {
    return (k >> 4) * 16 * N + (n >> 3) * 128 +
           ((n & 7) * 4 + ((k & 7) >> 1)) * 4 + ((k >> 3) & 1) * 2 + (k & 1);
}

__global__ __launch_bounds__(256) void convW(
    const float* __restrict__ Win, const float* __restrict__ Wq,
    const float* __restrict__ Wk, const float* __restrict__ Wv,
    const float* __restrict__ Wsk, const float* __restrict__ W1,
    const float* __restrict__ W2) {
    int i = blockIdx.x * blockDim.x + threadIdx.x;
    if (i >= TOTW) return;
    const float* src;
    int base, off, N, matsz;
    if (i < OFF_WQ)       { src = Win; base = 0;       off = i;           N = 128; matsz = HIDC * HIDC; }
    else if (i < OFF_WK)  { src = Wq;  base = OFF_WQ;  off = i - OFF_WQ;  N = 128; matsz = HIDC * HIDC; }
    else if (i < OFF_WV)  { src = Wk;  base = OFF_WK;  off = i - OFF_WK;  N = 128; matsz = HIDC * HIDC; }
    else if (i < OFF_WSK) { src = Wv;  base = OFF_WV;  off = i - OFF_WV;  N = 128; matsz = HIDC * HIDC; }
    else if (i < OFF_W1)  { src = Wsk; base = OFF_WSK; off = i - OFF_WSK; N = 128; matsz = HIDC * HIDC; }
    else if (i < OFF_W2)  { src = W1;  base = OFF_W1;  off = i - OFF_W1;  N = 256; matsz = HIDC * FFC; }
    else                  { src = W2;  base = OFF_W2;  off = i - OFF_W2;  N = 128; matsz = FFC * HIDC; }
    int l = off / matsz;
    int o2 = off - l * matsz;
    int k = o2 / N, n = o2 - k * N;
    g_wt[base + l * matsz + permW16(k, n, N)] = __float2half_rn(src[off]);
}

// ---------------- CSR build ----------------
__global__ __launch_bounds__(256) void k_clear_deg() {
    int i = blockIdx.x * blockDim.x + threadIdx.x;
    if (i < NN) g_deg[i] = 0;
}
__global__ __launch_bounds__(256) void k_hist() {
    int e = blockIdx.x * blockDim.x + threadIdx.x;
    if (e < EE) atomicAdd(&g_deg[g_dst[e]], 1);
}
__global__ __launch_bounds__(CHUNK) void k_chunksum() {
    __shared__ int sh[CHUNK];
    int tid = threadIdx.x;
    int i = blockIdx.x * CHUNK + tid;
    sh[tid] = (i < NN) ? g_deg[i] : 0;
    __syncthreads();
    for (int off = CHUNK / 2; off > 0; off >>= 1) {
        if (tid < off) sh[tid] += sh[tid + off];
        __syncthreads();
    }
    if (tid == 0) g_csums[blockIdx.x] = sh[0];
}
__global__ void k_scanchunks() {
    if (threadIdx.x == 0 && blockIdx.x == 0) {
        int run = 0;
        for (int c = 0; c < NCHK; c++) {
            int v = g_csums[c];
            g_csums[c] = run;
            run += v;
        }
        g_rowptr[NN] = run;
    }
}
__global__ __launch_bounds__(CHUNK) void k_rowptr() {
    __shared__ int sh[CHUNK];
    int tid = threadIdx.x;
    int i = blockIdx.x * CHUNK + tid;
    int v = (i < NN) ? g_deg[i] : 0;
    sh[tid] = v;
    __syncthreads();
    for (int off = 1; off < CHUNK; off <<= 1) {
        int t = (tid >= off) ? sh[tid - off] : 0;
        __syncthreads();
        sh[tid] += t;
        __syncthreads();
    }
    if (i < NN) {
        int excl = sh[tid] - v + g_csums[blockIdx.x];
        g_rowptr[i] = excl;
        g_cur[i] = excl;
    }
}
__global__ __launch_bounds__(256) void k_fill() {
    int e = blockIdx.x * blockDim.x + threadIdx.x;
    if (e >= EE) return;
    int slot = atomicAdd(&g_cur[g_dst[e]], 1);
    g_csrc[slot] = g_src[e];
}

// ---------------- FP16 GEMM (m16n8k16), BK=32, fragment-major smem -----------
#define BM 128
#define BN 128
#define BK 32
#define ABUF 4096   // halves per A buffer
#define BBUF 4096   // halves per B buffer

__device__ __forceinline__ void ldA(
    const float* __restrict__ A, int M, int K, int m0, int kc, int tid,
    float4 ar[4]) {
#pragma unroll
    for (int i = 0; i < 4; i++) {
        int f = tid + i * 256;
        int m = f >> 3, k4 = (f & 7) * 4;
        ar[i] = (m0 + m < M)
                    ? *(const float4*)(A + (size_t)(m0 + m) * K + kc + k4)
                    : make_float4(0.f, 0.f, 0.f, 0.f);
    }
}

__device__ __forceinline__ void stA(__half2* As2, int tid, const float4 ar[4]) {
#pragma unroll
    for (int i = 0; i < 4; i++) {
        int f = tid + i * 256;
        int m = f >> 3, k4 = (f & 7) * 4;
        int kc2 = k4 >> 4, k4r = k4 & 15;
        int g = m & 7, h = (m >> 3) & 1, mb = m >> 4;
        int t = (k4r & 7) >> 1;            // 0 or 2
        int kb = (k4r >> 3) & 1;
        int reg = h + 2 * kb;
        int cb = (kc2 * 8 + mb) * 128;     // chunk base in half2
        __half2 p0 = __floats2half2_rn(ar[i].x, ar[i].y);
        __half2 p1 = __floats2half2_rn(ar[i].z, ar[i].w);
        As2[cb + (g * 4 + t) * 4 + reg] = p0;
        As2[cb + (g * 4 + t + 1) * 4 + reg] = p1;
    }
}

__device__ __forceinline__ void cpB(uint32_t bs_addr, const __half* __restrict__ Bmat,
                                    int N, int n0, int kc, int tid) {
    const __half* gp0 = Bmat + (size_t)kc * N + (n0 >> 3) * 128;
    const __half* gp1 = Bmat + (size_t)(kc + 16) * N + (n0 >> 3) * 128;
#pragma unroll
    for (int i = 0; i < 2; i++) {
        int idx = tid + i * 256;           // 0..511
        const __half* gp = (idx < 256) ? (gp0 + idx * 8) : (gp1 + (idx - 256) * 8);
        cp16(bs_addr + idx * 16, gp);
    }
}

template <int ACT>
__device__ __forceinline__ void gemm_core(
    const float* __restrict__ A, const __half* __restrict__ Bmat,
    const float* __restrict__ bias, float* __restrict__ C,
    int M, int K, int Nld, int m0, int n0,
    __half* As, __half* Bs, uint32_t bs_addr) {
    int tid = threadIdx.x;
    int warp = tid >> 5, lane = tid & 31;
    int wm = (warp >> 2) * 64, wn = (warp & 3) * 32;

    float acc[4][4][4];
#pragma unroll
    for (int a = 0; a < 4; a++)
#pragma unroll
        for (int b = 0; b < 4; b++)
#pragma unroll
            for (int c = 0; c < 4; c++) acc[a][b][c] = 0.f;

    float4 ar[4];
    ldA(A, M, K, m0, 0, tid, ar);
    cpB(bs_addr, Bmat, Nld, n0, 0, tid);
    stA((__half2*)As, tid, ar);
    cp_commit();
    cp_wait0();
    __syncthreads();

    int nit = K / BK;
    for (int it = 0; it < nit; it++) {
        int cur = it & 1;
        const __half* Ac = As + cur * ABUF;
        const __half* Bc = Bs + cur * BBUF;
        if (it + 1 < nit) {
            ldA(A, M, K, m0, (it + 1) * BK, tid, ar);
            cpB(bs_addr + (cur ^ 1) * (BBUF * 2), Bmat, Nld, n0, (it + 1) * BK, tid);
            cp_commit();
        }

#pragma unroll
        for (int kc2 = 0; kc2 < 2; kc2++) {
            uint4 af[4];
#pragma unroll
            for (int tm = 0; tm < 4; tm++) {
                int mb = (wm >> 4) + tm;
                af[tm] = *(const uint4*)(Ac + (kc2 * 8 + mb) * 256 + lane * 8);
            }
            uint2 bf[4];
#pragma unroll
            for (int tn = 0; tn < 4; tn++) {
                int nb = (wn >> 3) + tn;
                bf[tn] = *(const uint2*)(Bc + (kc2 * 16 + nb) * 128 + lane * 4);
            }
#pragma unroll
            for (int tm = 0; tm < 4; tm++)
#pragma unroll
                for (int tn = 0; tn < 4; tn++)
                    mma_f16(acc[tm][tn], (const uint32_t*)&af[tm],
                            (const uint32_t*)&bf[tn]);
        }

        if (it + 1 < nit) stA((__half2*)(As + (cur ^ 1) * ABUF), tid, ar);
        cp_wait0();
        __syncthreads();
    }

    // epilogue
    int gg = lane >> 2, tt = lane & 3;
#pragma unroll
    for (int tm = 0; tm < 4; tm++) {
        int r0 = m0 + wm + tm * 16 + gg;
        int r1 = r0 + 8;
#pragma unroll
        for (int tn = 0; tn < 4; tn++) {
            int cb = n0 + wn + tn * 8 + 2 * tt;
            float b0 = __ldg(bias + cb);
            float b1 = __ldg(bias + cb + 1);
            float v00 = acc[tm][tn][0] + b0;
            float v01 = acc[tm][tn][1] + b1;
            float v10 = acc[tm][tn][2] + b0;
            float v11 = acc[tm][tn][3] + b1;
            if (ACT == 1) {
                v00 = fmaxf(v00, 0.f); v01 = fmaxf(v01, 0.f);
                v10 = fmaxf(v10, 0.f); v11 = fmaxf(v11, 0.f);
            }
            if (r0 < M) *(float2*)(C + (size_t)r0 * Nld + cb) = make_float2(v00, v01);
            if (r1 < M) *(float2*)(C + (size_t)r1 * Nld + cb) = make_float2(v10, v11);
        }
    }
}

template <int ACT>
__global__ __launch_bounds__(256, 2) void gemm_f16(
    const float* __restrict__ A, const __half* __restrict__ B,
    const float* __restrict__ bias, float* __restrict__ C,
    int M, int K, int Nld) {
    __shared__ __align__(16) __half As[2 * ABUF];
    __shared__ __align__(16) __half Bs[2 * BBUF];
    uint32_t bs = (uint32_t)__cvta_generic_to_shared(Bs);
    gemm_core<ACT>(A, B, bias, C, M, K, Nld, blockIdx.x * BM, blockIdx.y * BN,
                   As, Bs, bs);
}

// fused Q/K/V/SK projection: grid.y in [0,4) selects operator
__global__ __launch_bounds__(256, 2) void gemm_qkvsk(
    const float* __restrict__ A, const __half* __restrict__ wt,
    const float* __restrict__ bq, const float* __restrict__ bk,
    const float* __restrict__ bv, const float* __restrict__ bsk, int l) {
    __shared__ __align__(16) __half As[2 * ABUF];
    __shared__ __align__(16) __half Bs[2 * BBUF];
    uint32_t bs = (uint32_t)__cvta_generic_to_shared(Bs);
    const __half* B;
    const float* bias;
    float* C;
    switch (blockIdx.y) {
        case 0: B = wt + OFF_WQ;  bias = bq;  C = g_q;  break;
        case 1: B = wt + OFF_WK;  bias = bk;  C = g_k;  break;
        case 2: B = wt + OFF_WV;  bias = bv;  C = g_v;  break;
        default: B = wt + OFF_WSK; bias = bsk; C = g_sk; break;
    }
    B += (size_t)l * HIDC * HIDC;
    bias += l * HIDC;
    gemm_core<0>(A, B, bias, C, NN, HIDC, HIDC, blockIdx.x * BM, 0, As, Bs, bs);
}

// ---------------- fused FFN: u = gelu(h@W1+b1) @ W2 + b2, t kept in smem ------
__global__ __launch_bounds__(256) void ffn_fused(
    const float* __restrict__ h, const __half* __restrict__ W1f,
    const float* __restrict__ b1, const __half* __restrict__ W2f,
    const float* __restrict__ b2, float* __restrict__ u) {
    extern __shared__ __half dsm[];
    __half* tS = dsm;                 // 32768 halves
    __half* As = dsm + 32768;         // 8192
    __half* Bs = dsm + 40960;         // 8192
    uint32_t bs = (uint32_t)__cvta_generic_to_shared(Bs);
    __half2* tS2 = (__half2*)tS;

    int tid = threadIdx.x;
    int warp = tid >> 5, lane = tid & 31;
    int wm = (warp >> 2) * 64, wn = (warp & 3) * 32;
    int gg = lane >> 2, tt = lane & 3;
    int m0 = blockIdx.x * BM;

    // ---------------- phase 1: t = gelu(h @ W1 + b1), two 128-N tiles --------
    for (int half_n = 0; half_n < 2; half_n++) {
        int n0 = half_n * 128;
        float acc[4][4][4];
#pragma unroll
        for (int a = 0; a < 4; a++)
#pragma unroll
            for (int b = 0; b < 4; b++)
#pragma unroll
                for (int c = 0; c < 4; c++) acc[a][b][c] = 0.f;

        float4 ar[4];
        ldA(h, NN, HIDC, m0, 0, tid, ar);
        cpB(bs, W1f, FFC, n0, 0, tid);
        stA((__half2*)As, tid, ar);
        cp_commit();
        cp_wait0();
        __syncthreads();

        for (int it = 0; it < HIDC / BK; it++) {   // 4 iters
            int cur = it & 1;
            const __half* Ac = As + cur * ABUF;
            const __half* Bc = Bs + cur * BBUF;
            if (it + 1 < HIDC / BK) {
                ldA(h, NN, HIDC, m0, (it + 1) * BK, tid, ar);
                cpB(bs + (cur ^ 1) * (BBUF * 2), W1f, FFC, n0, (it + 1) * BK, tid);
                cp_commit();
            }
#pragma unroll
            for (int kc2 = 0; kc2 < 2; kc2++) {
                uint4 af[4];
#pragma unroll
                for (int tm = 0; tm < 4; tm++) {
                    int mb = (wm >> 4) + tm;
                    af[tm] = *(const uint4*)(Ac + (kc2 * 8 + mb) * 256 + lane * 8);
                }
                uint2 bf[4];
#pragma unroll
                for (int tn = 0; tn < 4; tn++) {
                    int nb = (wn >> 3) + tn;
                    bf[tn] = *(const uint2*)(Bc + (kc2 * 16 + nb) * 128 + lane * 4);
                }
#pragma unroll
                for (int tm = 0; tm < 4; tm++)
#pragma unroll
                    for (int tn = 0; tn < 4; tn++)
                        mma_f16(acc[tm][tn], (const uint32_t*)&af[tm],
                                (const uint32_t*)&bf[tn]);
            }
            if (it + 1 < HIDC / BK) stA((__half2*)(As + (cur ^ 1) * ABUF), tid, ar);
            cp_wait0();
            __syncthreads();
        }

        // epilogue: gelu, write to tS in A-fragment layout (K dim = t column)
#pragma unroll
        for (int tm = 0; tm < 4; tm++) {
            int mloc0 = wm + tm * 16 + gg;     // local rows
            int mloc1 = mloc0 + 8;
#pragma unroll
            for (int tn = 0; tn < 4; tn++) {
                int cb = n0 + wn + tn * 8 + 2 * tt;   // t column (0..255), even
                float b0 = __ldg(b1 + cb);
                float b1v = __ldg(b1 + cb + 1);
                float v00 = acc[tm][tn][0] + b0;
                float v01 = acc[tm][tn][1] + b1v;
                float v10 = acc[tm][tn][2] + b0;
                float v11 = acc[tm][tn][3] + b1v;
                v00 = 0.5f * v00 * (1.f + erff(v00 * 0.70710678118654752f));
                v01 = 0.5f * v01 * (1.f + erff(v01 * 0.70710678118654752f));
                v10 = 0.5f * v10 * (1.f + erff(v10 * 0.70710678118654752f));
                v11 = 0.5f * v11 * (1.f + erff(v11 * 0.70710678118654752f));
                int iter = cb >> 4, kk = cb & 15;
                int slot = (kk & 7) >> 1, kb = (kk >> 3) & 1;
                {
                    int g = mloc0 & 7, hh = (mloc0 >> 3) & 1, mb = mloc0 >> 4;
                    tS2[iter * 1024 + mb * 128 + (g * 4 + slot) * 4 + hh + 2 * kb] =
                        __floats2half2_rn(v00, v01);
                }
                {
                    int g = mloc1 & 7, hh = (mloc1 >> 3) & 1, mb = mloc1 >> 4;
                    tS2[iter * 1024 + mb * 128 + (g * 4 + slot) * 4 + hh + 2 * kb] =
                        __floats2half2_rn(v10, v11);
                }
            }
        }
        __syncthreads();
    }

    // ---------------- phase 2: u = t @ W2 + b2 (A from tS, K=256) ------------
    float acc[4][4][4];
#pragma unroll
    for (int a = 0; a < 4; a++)
#pragma unroll
        for (int b = 0; b < 4; b++)
#pragma unroll
            for (int c = 0; c < 4; c++) acc[a][b][c] = 0.f;

    cpB(bs, W2f, HIDC, 0, 0, tid);
    cp_commit();
    cp_wait0();
    __syncthreads();

    for (int it = 0; it < FFC / BK; it++) {   // 8 iters
        int cur = it & 1;
        const __half* Bc = Bs + cur * BBUF;
        if (it + 1 < FFC / BK) {
            cpB(bs + (cur ^ 1) * (BBUF * 2), W2f, HIDC, 0, (it + 1) * BK, tid);
            cp_commit();
        }
#pragma unroll
        for (int kc2 = 0; kc2 < 2; kc2++) {
            int iter = it * 2 + kc2;
            uint4 af[4];
#pragma unroll
            for (int tm = 0; tm < 4; tm++) {
                int mb = (wm >> 4) + tm;
                af[tm] = *(const uint4*)(tS + iter * 2048 + mb * 256 + lane * 8);
            }
            uint2 bf[4];
#pragma unroll
            for (int tn = 0; tn < 4; tn++) {
                int nb = (wn >> 3) + tn;
                bf[tn] = *(const uint2*)(Bc + (kc2 * 16 + nb) * 128 + lane * 4);
            }
#pragma unroll
            for (int tm = 0; tm < 4; tm++)
#pragma unroll
                for (int tn = 0; tn < 4; tn++)
                    mma_f16(acc[tm][tn], (const uint32_t*)&af[tm],
                            (const uint32_t*)&bf[tn]);
        }
        cp_wait0();
        __syncthreads();
    }

#pragma unroll
    for (int tm = 0; tm < 4; tm++) {
        int r0 = m0 + wm + tm * 16 + gg;
        int r1 = r0 + 8;
#pragma unroll
        for (int tn = 0; tn < 4; tn++) {
            int cb = wn + tn * 8 + 2 * tt;
            float b0 = __ldg(b2 + cb);
            float b1v = __ldg(b2 + cb + 1);
            float v00 = acc[tm][tn][0] + b0;
            float v01 = acc[tm][tn][1] + b1v;
            float v10 = acc[tm][tn][2] + b0;
            float v11 = acc[tm][tn][3] + b1v;
            if (r0 < NN) *(float2*)(u + (size_t)r0 * HIDC + cb) = make_float2(v00, v01);
            if (r1 < NN) *(float2*)(u + (size_t)r1 * HIDC + cb) = make_float2(v10, v11);
        }
    }
}

// ---- fused attention + LN1, 2 warps per node; PER-HEAD (m,l) merge -----------
__global__ __launch_bounds__(256) void attn_ln_fused(
    const float* __restrict__ g, const float* __restrict__ bt) {
    __shared__ float smA[4][128];
    __shared__ float smM[4][2], smL[4][2];

    int node = (blockIdx.x * blockDim.x + threadIdx.x) >> 6;
    if (node >= NN) return;   // never taken: grid covers NN exactly
    int sub = (threadIdx.x >> 5) & 1;
    int nloc = threadIdx.x >> 6;
    int lane = threadIdx.x & 31;
    int head = lane >> 4;

    int beg = g_rowptr[node], end = g_rowptr[node + 1];
    int cnt = end - beg;
    int mid = beg + ((cnt + 1) >> 1);
    int es = sub ? mid : beg;
    int ee = sub ? end : mid;

    size_t qb = (size_t)node * HIDC + lane * 4;
    float4 qv = *(const float4*)(g_q + qb);
    float m = -1e30f, l = 0.f;
    float4 acc = make_float4(0.f, 0.f, 0.f, 0.f);
    int e = es;
    for (; e + 1 < ee; e += 2) {
        int s0 = g_csrc[e], s1 = g_csrc[e + 1];
        size_t b0 = (size_t)s0 * HIDC + lane * 4;
        size_t b1 = (size_t)s1 * HIDC + lane * 4;
        float4 k0 = *(const float4*)(g_k + b0);
        float4 k1 = *(const float4*)(g_k + b1);
        float4 v0 = *(const float4*)(g_v + b0);
        float4 v1 = *(const float4*)(g_v + b1);
        float p0 = qv.x * k0.x + qv.y * k0.y + qv.z * k0.z + qv.w * k0.w;
        float p1 = qv.x * k1.x + qv.y * k1.y + qv.z * k1.z + qv.w * k1.w;
        p0 += __shfl_xor_sync(0xffffffffu, p0, 8, 16);
        p1 += __shfl_xor_sync(0xffffffffu, p1, 8, 16);
        p0 += __shfl_xor_sync(0xffffffffu, p0, 4, 16);
        p1 += __shfl_xor_sync(0xffffffffu, p1, 4, 16);
        p0 += __shfl_xor_sync(0xffffffffu, p0, 2, 16);
        p1 += __shfl_xor_sync(0xffffffffu, p1, 2, 16);
        p0 += __shfl_xor_sync(0xffffffffu, p0, 1, 16);
        p1 += __shfl_xor_sync(0xffffffffu, p1, 1, 16);
        float sc0 = p0 * 0.125f;
        float sc1 = p1 * 0.125f;
        float mn = fmaxf(m, fmaxf(sc0, sc1));
        float scale = __expf(m - mn);
        float w0 = __expf(sc0 - mn);
        float w1 = __expf(sc1 - mn);
        l = l * scale + w0 + w1;
        acc.x = acc.x * scale + w0 * v0.x + w1 * v1.x;
        acc.y = acc.y * scale + w0 * v0.y + w1 * v1.y;
        acc.z = acc.z * scale + w0 * v0.z + w1 * v1.z;
        acc.w = acc.w * scale + w0 * v0.w + w1 * v1.w;
        m = mn;
    }
    if (e < ee) {
        int s = g_csrc[e];
        size_t sb = (size_t)s * HIDC + lane * 4;
        float4 kv = *(const float4*)(g_k + sb);
        float4 vv = *(const float4*)(g_v + sb);
        float p = qv.x * kv.x + qv.y * kv.y + qv.z * kv.z + qv.w * kv.w;
        p += __shfl_xor_sync(0xffffffffu, p, 8, 16);
        p += __shfl_xor_sync(0xffffffffu, p, 4, 16);
        p += __shfl_xor_sync(0xffffffffu, p, 2, 16);
        p += __shfl_xor_sync(0xffffffffu, p, 1, 16);
        float sc = p * 0.125f;
        float mn = fmaxf(m, sc);
        float scale = __expf(m - mn);
        float w = __expf(sc - mn);
        l = l * scale + w;
        acc.x = acc.x * scale + w * vv.x;
        acc.y = acc.y * scale + w * vv.y;
        acc.z = acc.z * scale + w * vv.z;
        acc.w = acc.w * scale + w * vv.w;
        m = mn;
    }

    // warp-1 publishes its partial state (m,l are PER-HEAD: lanes 0 and 16)
    if (sub == 1) {
        *(float4*)&smA[nloc][lane * 4] = acc;
        if ((lane & 15) == 0) { smM[nloc][head] = m; smL[nloc][head] = l; }
    }
    __syncthreads();
    if (sub == 1) return;

    // warp-0 merges the two online-softmax states (per-head scalars)
    float m1 = smM[nloc][head], l1 = smL[nloc][head];
    float4 a1 = *(const float4*)&smA[nloc][lane * 4];
    float mn = fmaxf(m, m1);
    float s0 = __expf(m - mn);
    float s1 = __expf(m1 - mn);
    float ltot = l * s0 + l1 * s1;
    acc.x = acc.x * s0 + a1.x * s1;
    acc.y = acc.y * s0 + a1.y * s1;
    acc.z = acc.z * s0 + a1.z * s1;
    acc.w = acc.w * s0 + a1.w * s1;
    float inv = (ltot > 0.f) ? 1.f / ltot : 0.f;
    acc.x *= inv; acc.y *= inv; acc.z *= inv; acc.w *= inv;

    // --- fused LayerNorm-1: h = LN(z + attn + sk) * g + bt ---
    float4 a = *(const float4*)(g_z + qb);
    float4 c = *(const float4*)(g_sk + qb);
    float v0 = a.x + acc.x + c.x, v1 = a.y + acc.y + c.y;
    float v2 = a.z + acc.z + c.z, v3 = a.w + acc.w + c.w;
    float s = v0 + v1 + v2 + v3;
#pragma unroll
    for (int o = 16; o > 0; o >>= 1) s += __shfl_xor_sync(0xffffffffu, s, o);
    float mu = s * (1.f / HIDC);
    float d0 = v0 - mu, d1 = v1 - mu, d2 = v2 - mu, d3 = v3 - mu;
    float ss = d0 * d0 + d1 * d1 + d2 * d2 + d3 * d3;
#pragma unroll
    for (int o = 16; o > 0; o >>= 1) ss += __shfl_xor_sync(0xffffffffu, ss, o);
    float rs = rsqrtf(ss * (1.f / HIDC) + EPSLN);
    int col = lane * 4;
    float4 o4;
    o4.x = d0 * rs * g[col + 0] + bt[col + 0];
    o4.y = d1 * rs * g[col + 1] + bt[col + 1];
    o4.z = d2 * rs * g[col + 2] + bt[col + 2];
    o4.w = d3 * rs * g[col + 3] + bt[col + 3];
    *(float4*)(g_h + qb) = o4;
}

// z = relu(LN(h+u)); out += betas[li]*z
__global__ __launch_bounds__(256) void lnacc_kernel(
    const float* __restrict__ g, const float* __restrict__ bt,
    float* __restrict__ out, int li) {
    int row = (blockIdx.x * blockDim.x + threadIdx.x) >> 5;
    if (row >= NN) return;
    int lane = threadIdx.x & 31;
    size_t base = (size_t)row * HIDC + lane * 4;
    float4 a = *(const float4*)(g_h + base);
    float4 b = *(const float4*)(g_u + base);
    float v0 = a.x + b.x, v1 = a.y + b.y, v2 = a.z + b.z, v3 = a.w + b.w;
    float s = v0 + v1 + v2 + v3;
#pragma unroll
    for (int o = 16; o > 0; o >>= 1) s += __shfl_xor_sync(0xffffffffu, s, o);
    float mu = s * (1.f / HIDC);
    float d0 = v0 - mu, d1 = v1 - mu, d2 = v2 - mu, d3 = v3 - mu;
    float ss = d0 * d0 + d1 * d1 + d2 * d2 + d3 * d3;
#pragma unroll
    for (int o = 16; o > 0; o >>= 1) ss += __shfl_xor_sync(0xffffffffu, ss, o);
    float rs = rsqrtf(ss * (1.f / HIDC) + EPSLN);
    int col = lane * 4;
    float z0 = fmaxf(d0 * rs * g[col + 0] + bt[col + 0], 0.f);
    float z1 = fmaxf(d1 * rs * g[col + 1] + bt[col + 1], 0.f);
    float z2 = fmaxf(d2 * rs * g[col + 2] + bt[col + 2], 0.f);
    float z3 = fmaxf(d3 * rs * g[col + 3] + bt[col + 3], 0.f);
    float bb = g_betas[li];
    *(float4*)(g_z + base) = make_float4(z0, z1, z2, z3);
    float4 oo = *(float4*)(out + base);
    oo.x += bb * z0; oo.y += bb * z1; oo.z += bb * z2; oo.w += bb * z3;
    *(float4*)(out + base) = oo;
}

__global__ __launch_bounds__(256) void init_acc(float* __restrict__ out) {
    int i = blockIdx.x * blockDim.x + threadIdx.x;
    if (i < NN * HIDC) out[i] = g_betas[0] * g_z[i];
}

// ---------------- host launcher ----------------
extern "C" void kernel_launch(void* const* d_in, const int* in_sizes, int n_in,
                              void* d_out, int out_size) {
    const float* x    = (const float*)d_in[0];
    const void*  ei   = d_in[1];
    const float* Win  = (const float*)d_in[2];
    const float* b_in = (const float*)d_in[3];
    const float* Wq   = (const float*)d_in[4];
    const float* bq   = (const float*)d_in[5];
    const float* Wk   = (const float*)d_in[6];
    const float* bk   = (const float*)d_in[7];
    const float* Wv   = (const float*)d_in[8];
    const float* bv   = (const float*)d_in[9];
    const float* Wsk  = (const float*)d_in[10];
    const float* bsk  = (const float*)d_in[11];
    const float* W1   = (const float*)d_in[12];
    const float* b1   = (const float*)d_in[13];
    const float* W2   = (const float*)d_in[14];
    const float* b2   = (const float*)d_in[15];
    const float* g1   = (const float*)d_in[16];
    const float* bt1  = (const float*)d_in[17];
    const float* g2   = (const float*)d_in[18];
    const float* bt2  = (const float*)d_in[19];
    const float* beta = (const float*)d_in[20];
    float* out = (float*)d_out;

    float *z, *h, *u;
    __half* wt;
    cudaGetSymbolAddress((void**)&z, g_z);
    cudaGetSymbolAddress((void**)&h, g_h);
    cudaGetSymbolAddress((void**)&u, g_u);
    cudaGetSymbolAddress((void**)&wt, g_wt);

    const int FFN_SMEM = 98304;
    cudaFuncSetAttribute(ffn_fused, cudaFuncAttributeMaxDynamicSharedMemorySize,
                         FFN_SMEM);

    const int GM = (NN + BM - 1) / BM;  // 391

    sniff_kernel<<<1, 32>>>((const unsigned*)ei);                        // 0
    beta_softmax<<<1, 32>>>(beta);                                       // 1
    convW<<<(TOTW + 255) / 256, 256>>>(Win, Wq, Wk, Wv, Wsk, W1, W2);    // 2
    gemm_f16<1><<<dim3(GM, 1), 256>>>(x, wt, b_in, z, NN, HIDC, HIDC);   // 3
    gemm_qkvsk<<<dim3(GM, 4), 256>>>(z, wt, bq, bk, bv, bsk, 0);         // 4

    init_acc<<<(NN * HIDC + 255) / 256, 256>>>(out);
    convert_edges<<<(EE + 255) / 256, 256>>>(ei);

    // CSR build (once; needed before first attn)
    k_clear_deg<<<(NN + 255) / 256, 256>>>();
    k_hist<<<(EE + 255) / 256, 256>>>();
    k_chunksum<<<NCHK, CHUNK>>>();
    k_scanchunks<<<1, 32>>>();
    k_rowptr<<<NCHK, CHUNK>>>();
    k_fill<<<(EE + 255) / 256, 256>>>();

    for (int l = 0; l < NLAYERS; l++) {
        if (l > 0)
            gemm_qkvsk<<<dim3(GM, 4), 256>>>(z, wt, bq, bk, bv, bsk, l);

        attn_ln_fused<<<(NN * 64 + 255) / 256, 256>>>(g1 + l * HIDC, bt1 + l * HIDC);

        ffn_fused<<<GM, 256, FFN_SMEM>>>(
            h, wt + OFF_W1 + (size_t)l * HIDC * FFC, b1 + l * FFC,
            wt + OFF_W2 + (size_t)l * FFC * HIDC, b2 + l * HIDC, u);

        lnacc_kernel<<<(NN + 7) / 8, 256>>>(g2 + l * HIDC, bt2 + l * HIDC, out, l + 1);
    }
}